// round 9
// baseline (speedup 1.0000x reference)
#include <cuda_runtime.h>
#include <math.h>
#include <stdint.h>

#define BB   8
#define NN   2048
#define FIN  512
#define FOUT 256

// h stored PERMUTED (fragment-major chunks) + tf32-prerounded
__device__ float g_h[(size_t)BB * NN * FOUT];
__device__ float g_f[BB * NN];
__device__ float g_g[BB * NN];

__device__ __forceinline__ uint32_t to_tf32(float f) {
    uint32_t r; asm("cvt.rna.tf32.f32 %0, %1;" : "=r"(r) : "f"(f)); return r;
}
__device__ __forceinline__ void mma_tf32(float* d, const uint32_t* a, const uint32_t* b) {
    asm volatile(
        "mma.sync.aligned.m16n8k8.row.col.f32.tf32.tf32.f32 "
        "{%0,%1,%2,%3}, {%4,%5,%6,%7}, {%8,%9}, {%0,%1,%2,%3};"
        : "+f"(d[0]), "+f"(d[1]), "+f"(d[2]), "+f"(d[3])
        : "r"(a[0]), "r"(a[1]), "r"(a[2]), "r"(a[3]), "r"(b[0]), "r"(b[1]));
}
__device__ __forceinline__ uint32_t smem_u32(const void* p) {
    uint32_t a;
    asm("{ .reg .u64 t; cvta.to.shared.u64 t, %1; cvt.u32.u64 %0, t; }" : "=r"(a) : "l"(p));
    return a;
}
__device__ __forceinline__ void cp16(uint32_t dst, const void* src) {
    asm volatile("cp.async.cg.shared.global [%0], [%1], 16;" :: "r"(dst), "l"(src));
}
#define CP_COMMIT() asm volatile("cp.async.commit_group;" ::: "memory")
#define CP_WAIT0()  asm volatile("cp.async.wait_group 0;" ::: "memory")

// column permutation: o = wo*32 + na*8 + g  ->  float offset within 256-row
__host__ __device__ __forceinline__ int permo(int o) {
    int g = o & 7, na = (o >> 3) & 3, w = o >> 5;
    return (g >> 1) * 64 + (w >> 2) * 32 + (g & 1) * 16 + (w & 3) * 4 + na;
}

// ===========================================================================
// Kernel 1: h = x @ W via split-tf32 mma (3 MMAs) + fused f/g.  (R4 core)
// Epilogue now writes h PERMUTED (permo) + tf32-prerounded, scalar STG.
// 128 blocks x 512 threads.
// ===========================================================================
#define XS_OFF 0
#define XS_SZ  2560
#define WS_OFF 5120
#define WS_SZ  4224
#define GH_SMEM 54272

__global__ __launch_bounds__(512, 1)
void gemm_h_kernel(const float* __restrict__ x, const float* __restrict__ W,
                   const float* __restrict__ a)
{
    extern __shared__ float sm[];
    const uint32_t sb = smem_u32(sm);

    const int t    = threadIdx.x;
    const int m0   = blockIdx.x * 128;
    const int warp = t >> 5, lane = t & 31;
    const int g    = lane >> 2, tig = lane & 3;
    const int wi   = warp >> 2, wo = warp & 3;

    const int xrow = t >> 2, xseg = (t & 3) * 4;
    const int wrow = t >> 5, wseg = (t & 31) * 8;
    const float* xsrc = x + (size_t)(m0 + xrow) * FIN + xseg;
    const float* wsrc = W + (size_t)wrow * FOUT + wseg;

    auto issue = [&](int s) {
        uint32_t xd = sb + (XS_OFF + (s & 1) * XS_SZ + xrow * 20 + xseg) * 4;
        cp16(xd, xsrc + s * 16);
        uint32_t wd = sb + (WS_OFF + (s & 1) * WS_SZ + wrow * 264 + wseg) * 4;
        cp16(wd,      wsrc + (size_t)s * 16 * FOUT);
        cp16(wd + 16, wsrc + (size_t)s * 16 * FOUT + 4);
        CP_COMMIT();
    };

    float acc[2][8][4];
    #pragma unroll
    for (int ma = 0; ma < 2; ma++)
        #pragma unroll
        for (int na = 0; na < 8; na++)
            #pragma unroll
            for (int c = 0; c < 4; c++) acc[ma][na][c] = 0.f;

    issue(0);
    CP_WAIT0();
    __syncthreads();

    for (int s = 0; s < 32; s++) {
        if (s < 31) issue(s + 1);
        const float* xs = sm + XS_OFF + (s & 1) * XS_SZ;
        const float* ws = sm + WS_OFF + (s & 1) * WS_SZ;

        #pragma unroll
        for (int ks = 0; ks < 2; ks++) {
            uint32_t bhi[8][2], blo[8][2];
            #pragma unroll
            for (int na = 0; na < 8; na++) {
                int o = wo * 64 + na * 8 + g;
                float r0 = ws[(ks * 8 + tig) * 264 + o];
                float r1 = ws[(ks * 8 + tig + 4) * 264 + o];
                bhi[na][0] = to_tf32(r0);
                blo[na][0] = to_tf32(r0 - __uint_as_float(bhi[na][0]));
                bhi[na][1] = to_tf32(r1);
                blo[na][1] = to_tf32(r1 - __uint_as_float(bhi[na][1]));
            }
            #pragma unroll
            for (int ma = 0; ma < 2; ma++) {
                int R = wi * 32 + ma * 16;
                float r0 = xs[(R + g) * 20 + ks * 8 + tig];
                float r1 = xs[(R + g + 8) * 20 + ks * 8 + tig];
                float r2 = xs[(R + g) * 20 + ks * 8 + tig + 4];
                float r3 = xs[(R + g + 8) * 20 + ks * 8 + tig + 4];
                uint32_t ahi[4], alo[4];
                ahi[0] = to_tf32(r0); alo[0] = to_tf32(r0 - __uint_as_float(ahi[0]));
                ahi[1] = to_tf32(r1); alo[1] = to_tf32(r1 - __uint_as_float(ahi[1]));
                ahi[2] = to_tf32(r2); alo[2] = to_tf32(r2 - __uint_as_float(ahi[2]));
                ahi[3] = to_tf32(r3); alo[3] = to_tf32(r3 - __uint_as_float(ahi[3]));
                #pragma unroll
                for (int na = 0; na < 8; na++) {
                    mma_tf32(acc[ma][na], ahi, bhi[na]);
                    mma_tf32(acc[ma][na], alo, bhi[na]);
                    mma_tf32(acc[ma][na], ahi, blo[na]);
                }
            }
        }
        if (s < 31) CP_WAIT0();
        __syncthreads();
    }

    float a1c[16], a2c[16];
    #pragma unroll
    for (int na = 0; na < 8; na++) {
        int col = wo * 64 + na * 8 + tig * 2;
        a1c[2*na]   = __ldg(a + col);
        a1c[2*na+1] = __ldg(a + col + 1);
        a2c[2*na]   = __ldg(a + FOUT + col);
        a2c[2*na+1] = __ldg(a + FOUT + col + 1);
    }
    float* fred = sm;
    float* gred = sm + 512;

    #pragma unroll
    for (int ma = 0; ma < 2; ma++) {
        int ra = wi * 32 + ma * 16 + g;
        int rb = ra + 8;
        float fA = 0.f, gA = 0.f, fB = 0.f, gB = 0.f;
        float* hra = g_h + (size_t)(m0 + ra) * FOUT;
        float* hrb = g_h + (size_t)(m0 + rb) * FOUT;
        #pragma unroll
        for (int na = 0; na < 8; na++) {
            int col = wo * 64 + na * 8 + tig * 2;
            int p0 = permo(col), p1 = permo(col + 1);
            float c0 = acc[ma][na][0], c1 = acc[ma][na][1];
            float c2 = acc[ma][na][2], c3 = acc[ma][na][3];
            hra[p0] = __uint_as_float(to_tf32(c0));
            hra[p1] = __uint_as_float(to_tf32(c1));
            hrb[p0] = __uint_as_float(to_tf32(c2));
            hrb[p1] = __uint_as_float(to_tf32(c3));
            fA += c0 * a1c[2*na] + c1 * a1c[2*na+1];
            gA += c0 * a2c[2*na] + c1 * a2c[2*na+1];
            fB += c2 * a1c[2*na] + c3 * a1c[2*na+1];
            gB += c2 * a2c[2*na] + c3 * a2c[2*na+1];
        }
        fA += __shfl_xor_sync(0xffffffffu, fA, 1); fA += __shfl_xor_sync(0xffffffffu, fA, 2);
        gA += __shfl_xor_sync(0xffffffffu, gA, 1); gA += __shfl_xor_sync(0xffffffffu, gA, 2);
        fB += __shfl_xor_sync(0xffffffffu, fB, 1); fB += __shfl_xor_sync(0xffffffffu, fB, 2);
        gB += __shfl_xor_sync(0xffffffffu, gB, 1); gB += __shfl_xor_sync(0xffffffffu, gB, 2);
        if (tig == 0) {
            fred[wo * 128 + ra] = fA; fred[wo * 128 + rb] = fB;
            gred[wo * 128 + ra] = gA; gred[wo * 128 + rb] = gB;
        }
    }
    __syncthreads();
    if (t < 128) {
        float fv = fred[t] + fred[128 + t] + fred[256 + t] + fred[384 + t];
        float gv = gred[t] + gred[128 + t] + gred[256 + t] + gred[384 + t];
        g_f[m0 + t] = fv;
        g_g[m0 + t] = gv;
    }
}

// ===========================================================================
// Kernel 2: attention, mma.sync tf32. 1024 threads: warp grid 4(i) x 8(o),
// warp tile 32x32, acc 32 regs. Fragment-major smem layouts:
//   ps pitch 40, j stored as ks*8 + tig*2 + c  -> A frags via LDS.64
//   hs pitch 260, cols pre-permuted in gmem    -> B frags via LDS.128
// smem floats: dsum[1024]@0 | gs[2048]@1024 | ps[2][128*40]@3072 | hs[2][32*260]@13312
// ===========================================================================
#define AT_DSUM 0
#define AT_GS   1024
#define AT_PS0  3072
#define AT_PS1  8192
#define AT_HS0  13312
#define AT_HS1  21632
#define AT_HS_SZ 8320
#define ATTN_SMEM (29952 * 4)

__global__ __launch_bounds__(1024, 1)
void attn_kernel(const int* __restrict__ adj, float* __restrict__ out)
{
    extern __shared__ float smf[];
    const uint32_t sb = smem_u32(smf);

    const int t    = threadIdx.x;
    const int b    = blockIdx.x >> 4;
    const int i0   = (blockIdx.x & 15) << 7;
    const int warp = t >> 5, lane = t & 31;
    const int g    = lane >> 2, tig = lane & 3;
    const int wiq  = warp >> 3, wo = warp & 7;   // wiq 0..3, wo 0..7

    // consumer chunk offset (const per thread)
    const int myco = (g >> 1) * 64 + (wo >> 2) * 32 + (g & 1) * 16 + (wo & 3) * 4;

    // producer roles: 8 threads per p-row; thread covers within8=jq, ks=0..3
    const int irow = t >> 3;                     // 0..127
    const int jq   = t & 7;                      // within-8 j index
    const int tig2c = (jq & 3) * 2 + (jq >> 2);  // perm column base

    for (int j = t; j < NN; j += 1024) smf[AT_GS + j] = g_g[b * NN + j];
    const float fv = g_f[b * NN + i0 + irow];
    const int*   adjrow = adj + ((size_t)b * NN + i0 + irow) * NN + jq;
    const float* hb     = g_h + (size_t)b * NN * FOUT;

    // h-copy roles: thread copies 2 chunks of one row
    const int hrow = t >> 5;             // warp id = row 0..31
    const int hfo  = (lane * 2) * 4;     // float offset of first chunk

    float acc[2][4][4];
    #pragma unroll
    for (int ma = 0; ma < 2; ma++)
        #pragma unroll
        for (int na = 0; na < 4; na++)
            #pragma unroll
            for (int c = 0; c < 4; c++) acc[ma][na][c] = 0.f;
    float dloc = 0.f;

    auto cp_h = [&](int jt) {
        const float* src = hb + (size_t)(jt * 32 + hrow) * FOUT + hfo;
        uint32_t dst = sb + (AT_HS0 + (jt & 1) * AT_HS_SZ + hrow * 260 + hfo) * 4;
        cp16(dst,      src);
        cp16(dst + 16, src + 4);
        CP_COMMIT();
    };
    auto ld_adj = [&](int jtp, int* av) {
        #pragma unroll
        for (int l = 0; l < 4; l++) av[l] = adjrow[jtp * 32 + 8 * l];
    };
    auto store_p = [&](int jtp, const int* av) {
        float* ps = smf + (jtp & 1 ? AT_PS1 : AT_PS0) + irow * 40 + tig2c;
        const float* gsr = smf + AT_GS + jtp * 32 + jq;
        #pragma unroll
        for (int l = 0; l < 4; l++) {
            float z = fv + gsr[8 * l];
            z = z >= 0.f ? z : 0.2f * z;
            float p = (av[l] > 0) ? __expf(z) : 0.f;
            dloc += p;
            ps[8 * l] = __uint_as_float(to_tf32(p));
        }
    };
    auto do_mma = [&](int jt) {
        const float* ps = smf + (jt & 1 ? AT_PS1 : AT_PS0);
        const float* hs = smf + (jt & 1 ? AT_HS1 : AT_HS0);
        #pragma unroll
        for (int ks = 0; ks < 4; ks++) {
            uint32_t afr[2][4];
            #pragma unroll
            for (int ma = 0; ma < 2; ma++) {
                int R = wiq * 32 + ma * 16 + g;
                float2 lo = *(const float2*)(ps + R * 40 + ks * 8 + tig * 2);
                float2 hi = *(const float2*)(ps + (R + 8) * 40 + ks * 8 + tig * 2);
                afr[ma][0] = __float_as_uint(lo.x);
                afr[ma][1] = __float_as_uint(hi.x);
                afr[ma][2] = __float_as_uint(lo.y);
                afr[ma][3] = __float_as_uint(hi.y);
            }
            float4 c0 = *(const float4*)(hs + (ks * 8 + tig) * 260 + myco);
            float4 c1 = *(const float4*)(hs + (ks * 8 + tig + 4) * 260 + myco);
            uint32_t bfr[4][2] = {
                {__float_as_uint(c0.x), __float_as_uint(c1.x)},
                {__float_as_uint(c0.y), __float_as_uint(c1.y)},
                {__float_as_uint(c0.z), __float_as_uint(c1.z)},
                {__float_as_uint(c0.w), __float_as_uint(c1.w)}};
            #pragma unroll
            for (int ma = 0; ma < 2; ma++)
                #pragma unroll
                for (int na = 0; na < 4; na++)
                    mma_tf32(acc[ma][na], afr[ma], bfr[na]);
        }
    };

    // ---- prologue ----
    int A0[4], A1[4];
    cp_h(0);
    ld_adj(0, A0);
    ld_adj(1, A1);
    CP_WAIT0();
    __syncthreads();
    store_p(0, A0);
    ld_adj(2, A0);
    __syncthreads();

    // ---- main loop (x2 unroll for adj register ping-pong) ----
    for (int jt = 0; jt < 64; jt += 2) {
        {
            if (jt < 63) cp_h(jt + 1);
            do_mma(jt);
            if (jt < 63) store_p(jt + 1, A1);
            if (jt + 3 < 64) ld_adj(jt + 3, A1);
            if (jt < 63) CP_WAIT0();
            __syncthreads();
        }
        {
            int jo = jt + 1;
            if (jo < 63) cp_h(jo + 1);
            do_mma(jo);
            if (jo < 63) store_p(jo + 1, A0);
            if (jo + 3 < 64) ld_adj(jo + 3, A0);
            if (jo < 63) CP_WAIT0();
            __syncthreads();
        }
    }

    smf[AT_DSUM + jq * 128 + irow] = dloc;
    __syncthreads();

    #pragma unroll
    for (int ma = 0; ma < 2; ma++) {
        int ra = wiq * 32 + ma * 16 + g;
        int rb = ra + 8;
        float da = 0.f, db = 0.f;
        #pragma unroll
        for (int s = 0; s < 8; s++) {
            da += smf[AT_DSUM + s * 128 + ra];
            db += smf[AT_DSUM + s * 128 + rb];
        }
        float inva = (da > 0.f) ? 1.f / da : 0.f;
        float invb = (db > 0.f) ? 1.f / db : 0.f;
        float* outa = out + ((size_t)b * NN + i0 + ra) * FOUT;
        float* outb = out + ((size_t)b * NN + i0 + rb) * FOUT;
        #pragma unroll
        for (int na = 0; na < 4; na++) {
            int col = wo * 32 + na * 8 + tig * 2;
            float v0 = acc[ma][na][0] * inva;
            float v1 = acc[ma][na][1] * inva;
            float v2 = acc[ma][na][2] * invb;
            float v3 = acc[ma][na][3] * invb;
            v0 = v0 > 0.f ? v0 : expm1f(v0);
            v1 = v1 > 0.f ? v1 : expm1f(v1);
            v2 = v2 > 0.f ? v2 : expm1f(v2);
            v3 = v3 > 0.f ? v3 : expm1f(v3);
            *(float2*)(outa + col) = make_float2(v0, v1);
            *(float2*)(outb + col) = make_float2(v2, v3);
        }
    }
}

// ---------------------------------------------------------------------------
extern "C" void kernel_launch(void* const* d_in, const int* in_sizes, int n_in,
                              void* d_out, int out_size)
{
    const float* x   = (const float*)d_in[0];
    const int*   adj = (const int*)d_in[1];
    const float* W   = (const float*)d_in[2];
    const float* a   = (const float*)d_in[3];
    float*       out = (float*)d_out;

    cudaFuncSetAttribute(gemm_h_kernel, cudaFuncAttributeMaxDynamicSharedMemorySize, GH_SMEM);
    cudaFuncSetAttribute(attn_kernel,   cudaFuncAttributeMaxDynamicSharedMemorySize, ATTN_SMEM);

    gemm_h_kernel<<<128, 512, GH_SMEM>>>(x, W, a);
    attn_kernel<<<128, 1024, ATTN_SMEM>>>(adj, out);
}

// round 11
// speedup vs baseline: 1.4520x; 1.4520x over previous
#include <cuda_runtime.h>
#include <math.h>
#include <stdint.h>

#define BB   8
#define NN   2048
#define FIN  512
#define FOUT 256

__device__ float g_h[(size_t)BB * NN * FOUT];   // tf32-prerounded h, 16.8 MB
__device__ float g_f[BB * NN];
__device__ float g_g[BB * NN];

__device__ __forceinline__ uint32_t to_tf32(float f) {
    uint32_t r; asm("cvt.rna.tf32.f32 %0, %1;" : "=r"(r) : "f"(f)); return r;
}
__device__ __forceinline__ void mma_tf32(float* d, const uint32_t* a, const uint32_t* b) {
    asm volatile(
        "mma.sync.aligned.m16n8k8.row.col.f32.tf32.tf32.f32 "
        "{%0,%1,%2,%3}, {%4,%5,%6,%7}, {%8,%9}, {%0,%1,%2,%3};"
        : "+f"(d[0]), "+f"(d[1]), "+f"(d[2]), "+f"(d[3])
        : "r"(a[0]), "r"(a[1]), "r"(a[2]), "r"(a[3]), "r"(b[0]), "r"(b[1]));
}
__device__ __forceinline__ uint32_t smem_u32(const void* p) {
    uint32_t a;
    asm("{ .reg .u64 t; cvta.to.shared.u64 t, %1; cvt.u32.u64 %0, t; }" : "=r"(a) : "l"(p));
    return a;
}
__device__ __forceinline__ void cp16(uint32_t dst, const void* src) {
    asm volatile("cp.async.cg.shared.global [%0], [%1], 16;" :: "r"(dst), "l"(src));
}
#define CP_COMMIT() asm volatile("cp.async.commit_group;" ::: "memory")
#define CP_WAIT0()  asm volatile("cp.async.wait_group 0;" ::: "memory")

// ===========================================================================
// Kernel 1: h = x @ W via split-tf32 mma (3 MMAs) + fused f/g.  (R8, proven)
// h stored PRE-ROUNDED to tf32 (f/g reduced from full fp32 accumulators).
// 128 blocks x 512 threads.
// ===========================================================================
#define XS_OFF 0
#define XS_SZ  2560
#define WS_OFF 5120
#define WS_SZ  4224
#define GH_SMEM 54272

__global__ __launch_bounds__(512, 1)
void gemm_h_kernel(const float* __restrict__ x, const float* __restrict__ W,
                   const float* __restrict__ a)
{
    extern __shared__ float sm[];
    const uint32_t sb = smem_u32(sm);

    const int t    = threadIdx.x;
    const int m0   = blockIdx.x * 128;
    const int warp = t >> 5, lane = t & 31;
    const int g    = lane >> 2, tig = lane & 3;
    const int wi   = warp >> 2, wo = warp & 3;

    const int xrow = t >> 2, xseg = (t & 3) * 4;
    const int wrow = t >> 5, wseg = (t & 31) * 8;
    const float* xsrc = x + (size_t)(m0 + xrow) * FIN + xseg;
    const float* wsrc = W + (size_t)wrow * FOUT + wseg;

    auto issue = [&](int s) {
        uint32_t xd = sb + (XS_OFF + (s & 1) * XS_SZ + xrow * 20 + xseg) * 4;
        cp16(xd, xsrc + s * 16);
        uint32_t wd = sb + (WS_OFF + (s & 1) * WS_SZ + wrow * 264 + wseg) * 4;
        cp16(wd,      wsrc + (size_t)s * 16 * FOUT);
        cp16(wd + 16, wsrc + (size_t)s * 16 * FOUT + 4);
        CP_COMMIT();
    };

    float acc[2][8][4];
    #pragma unroll
    for (int ma = 0; ma < 2; ma++)
        #pragma unroll
        for (int na = 0; na < 8; na++)
            #pragma unroll
            for (int c = 0; c < 4; c++) acc[ma][na][c] = 0.f;

    issue(0);
    CP_WAIT0();
    __syncthreads();

    for (int s = 0; s < 32; s++) {
        if (s < 31) issue(s + 1);
        const float* xs = sm + XS_OFF + (s & 1) * XS_SZ;
        const float* ws = sm + WS_OFF + (s & 1) * WS_SZ;

        #pragma unroll
        for (int ks = 0; ks < 2; ks++) {
            uint32_t bhi[8][2], blo[8][2];
            #pragma unroll
            for (int na = 0; na < 8; na++) {
                int o = wo * 64 + na * 8 + g;
                float r0 = ws[(ks * 8 + tig) * 264 + o];
                float r1 = ws[(ks * 8 + tig + 4) * 264 + o];
                bhi[na][0] = to_tf32(r0);
                blo[na][0] = to_tf32(r0 - __uint_as_float(bhi[na][0]));
                bhi[na][1] = to_tf32(r1);
                blo[na][1] = to_tf32(r1 - __uint_as_float(bhi[na][1]));
            }
            #pragma unroll
            for (int ma = 0; ma < 2; ma++) {
                int R = wi * 32 + ma * 16;
                float r0 = xs[(R + g) * 20 + ks * 8 + tig];
                float r1 = xs[(R + g + 8) * 20 + ks * 8 + tig];
                float r2 = xs[(R + g) * 20 + ks * 8 + tig + 4];
                float r3 = xs[(R + g + 8) * 20 + ks * 8 + tig + 4];
                uint32_t ahi[4], alo[4];
                ahi[0] = to_tf32(r0); alo[0] = to_tf32(r0 - __uint_as_float(ahi[0]));
                ahi[1] = to_tf32(r1); alo[1] = to_tf32(r1 - __uint_as_float(ahi[1]));
                ahi[2] = to_tf32(r2); alo[2] = to_tf32(r2 - __uint_as_float(ahi[2]));
                ahi[3] = to_tf32(r3); alo[3] = to_tf32(r3 - __uint_as_float(ahi[3]));
                #pragma unroll
                for (int na = 0; na < 8; na++) {
                    mma_tf32(acc[ma][na], ahi, bhi[na]);
                    mma_tf32(acc[ma][na], alo, bhi[na]);
                    mma_tf32(acc[ma][na], ahi, blo[na]);
                }
            }
        }
        if (s < 31) CP_WAIT0();
        __syncthreads();
    }

    float a1c[16], a2c[16];
    #pragma unroll
    for (int na = 0; na < 8; na++) {
        int col = wo * 64 + na * 8 + tig * 2;
        a1c[2*na]   = __ldg(a + col);
        a1c[2*na+1] = __ldg(a + col + 1);
        a2c[2*na]   = __ldg(a + FOUT + col);
        a2c[2*na+1] = __ldg(a + FOUT + col + 1);
    }
    float* fred = sm;
    float* gred = sm + 512;

    #pragma unroll
    for (int ma = 0; ma < 2; ma++) {
        int ra = wi * 32 + ma * 16 + g;
        int rb = ra + 8;
        float fA = 0.f, gA = 0.f, fB = 0.f, gB = 0.f;
        #pragma unroll
        for (int na = 0; na < 8; na++) {
            int col = wo * 64 + na * 8 + tig * 2;
            float c0 = acc[ma][na][0], c1 = acc[ma][na][1];
            float c2 = acc[ma][na][2], c3 = acc[ma][na][3];
            float2 sA = make_float2(__uint_as_float(to_tf32(c0)), __uint_as_float(to_tf32(c1)));
            float2 sB = make_float2(__uint_as_float(to_tf32(c2)), __uint_as_float(to_tf32(c3)));
            *(float2*)(g_h + (size_t)(m0 + ra) * FOUT + col) = sA;
            *(float2*)(g_h + (size_t)(m0 + rb) * FOUT + col) = sB;
            fA += c0 * a1c[2*na] + c1 * a1c[2*na+1];
            gA += c0 * a2c[2*na] + c1 * a2c[2*na+1];
            fB += c2 * a1c[2*na] + c3 * a1c[2*na+1];
            gB += c2 * a2c[2*na] + c3 * a2c[2*na+1];
        }
        fA += __shfl_xor_sync(0xffffffffu, fA, 1); fA += __shfl_xor_sync(0xffffffffu, fA, 2);
        gA += __shfl_xor_sync(0xffffffffu, gA, 1); gA += __shfl_xor_sync(0xffffffffu, gA, 2);
        fB += __shfl_xor_sync(0xffffffffu, fB, 1); fB += __shfl_xor_sync(0xffffffffu, fB, 2);
        gB += __shfl_xor_sync(0xffffffffu, gB, 1); gB += __shfl_xor_sync(0xffffffffu, gB, 2);
        if (tig == 0) {
            fred[wo * 128 + ra] = fA; fred[wo * 128 + rb] = fB;
            gred[wo * 128 + ra] = gA; gred[wo * 128 + rb] = gB;
        }
    }
    __syncthreads();
    if (t < 128) {
        float fv = fred[t] + fred[128 + t] + fred[256 + t] + fred[384 + t];
        float gv = gred[t] + gred[128 + t] + gred[256 + t] + gred[384 + t];
        g_f[m0 + t] = fv;
        g_g[m0 + t] = gv;
    }
}

// ===========================================================================
// Kernel 2: attention, mma.sync tf32. 1024 threads.
// Warp grid 4(i) x 8(o) — minimizes smem crossbar traffic:
//   Wo*A_tile + Wi*B_tile = 8*16KB + 4*32KB = 256KB/jt (R8 was 320KB).
// Producer/ps/hs layouts IDENTICAL to R8 (proven conflict-free).
// smem floats: dsum[1024]@0 | gs[2048]@1024 | ps[2][128*36]@3072 | hs[2][32*264]@12288
// ===========================================================================
#define AT_DSUM 0
#define AT_GS   1024
#define AT_PS0  3072
#define AT_PS1  7680
#define AT_HS0  12288
#define AT_HS1  20736
#define AT_HS_SZ 8448
#define ATTN_SMEM (29184 * 4)

__global__ __launch_bounds__(1024, 1)
void attn_kernel(const int* __restrict__ adj, float* __restrict__ out)
{
    extern __shared__ float smf[];
    const uint32_t sb = smem_u32(smf);

    const int t    = threadIdx.x;
    const int b    = blockIdx.x >> 4;
    const int i0   = (blockIdx.x & 15) << 7;
    const int warp = t >> 5, lane = t & 31;
    const int g    = lane >> 2, tig = lane & 3;
    const int wiq  = warp >> 3, wo = warp & 7;   // wiq 0..3 (i), wo 0..7 (o)

    // producer roles: 8 threads per p-row, 4 j each (R8 exact)
    const int irow = t >> 3;        // 0..127
    const int jq   = t & 7;         // j-eighth of 32 (4 each)
    const int hjr  = t >> 5;        // 0..31 (h row)
    const int hoc  = (t & 31) * 8;  // h col base (8 floats = 2 cp16)

    for (int j = t; j < NN; j += 1024) smf[AT_GS + j] = g_g[b * NN + j];
    const float fv = g_f[b * NN + i0 + irow];
    const int*   adjrow = adj + ((size_t)b * NN + i0 + irow) * NN + jq * 4;
    const float* hb     = g_h + (size_t)b * NN * FOUT;

    float acc[2][4][4];
    #pragma unroll
    for (int ma = 0; ma < 2; ma++)
        #pragma unroll
        for (int na = 0; na < 4; na++)
            #pragma unroll
            for (int c = 0; c < 4; c++) acc[ma][na][c] = 0.f;
    float dloc = 0.f;

    auto cp_h = [&](int jt) {
        const float* src = hb + (size_t)(jt * 32 + hjr) * FOUT + hoc;
        uint32_t dst = sb + (AT_HS0 + (jt & 1) * AT_HS_SZ + hjr * 264 + hoc) * 4;
        cp16(dst,      src);
        cp16(dst + 16, src + 4);
        CP_COMMIT();
    };
    auto ld_adj = [&](int jtp, int4& av) {
        av = *(const int4*)(adjrow + jtp * 32);
    };
    auto store_p = [&](int jtp, const int4& v) {
        float* ps = smf + (jtp & 1 ? AT_PS1 : AT_PS0);
        const float* gsr = smf + AT_GS + jtp * 32 + jq * 4;
        float z0 = fv + gsr[0]; z0 = z0 >= 0.f ? z0 : 0.2f * z0;
        float z1 = fv + gsr[1]; z1 = z1 >= 0.f ? z1 : 0.2f * z1;
        float z2 = fv + gsr[2]; z2 = z2 >= 0.f ? z2 : 0.2f * z2;
        float z3 = fv + gsr[3]; z3 = z3 >= 0.f ? z3 : 0.2f * z3;
        float p0 = (v.x > 0) ? __expf(z0) : 0.f;
        float p1 = (v.y > 0) ? __expf(z1) : 0.f;
        float p2 = (v.z > 0) ? __expf(z2) : 0.f;
        float p3 = (v.w > 0) ? __expf(z3) : 0.f;
        dloc += p0 + p1 + p2 + p3;
        float4 st = make_float4(__uint_as_float(to_tf32(p0)),
                                __uint_as_float(to_tf32(p1)),
                                __uint_as_float(to_tf32(p2)),
                                __uint_as_float(to_tf32(p3)));
        *(float4*)(ps + irow * 36 + jq * 4) = st;
    };
    auto do_mma = [&](int jt) {
        const uint32_t* psu = (const uint32_t*)(smf + (jt & 1 ? AT_PS1 : AT_PS0));
        const uint32_t* hsu = (const uint32_t*)(smf + (jt & 1 ? AT_HS1 : AT_HS0));
        #pragma unroll
        for (int ks = 0; ks < 4; ks++) {
            uint32_t afr[2][4];
            #pragma unroll
            for (int ma = 0; ma < 2; ma++) {
                int base = (wiq * 32 + ma * 16 + g) * 36 + ks * 8 + tig;
                afr[ma][0] = psu[base];
                afr[ma][1] = psu[base + 8 * 36];
                afr[ma][2] = psu[base + 4];
                afr[ma][3] = psu[base + 8 * 36 + 4];
            }
            uint32_t bfr[4][2];
            #pragma unroll
            for (int na = 0; na < 4; na++) {
                int o = wo * 32 + na * 8 + g;
                bfr[na][0] = hsu[(ks * 8 + tig) * 264 + o];
                bfr[na][1] = hsu[(ks * 8 + tig + 4) * 264 + o];
            }
            #pragma unroll
            for (int ma = 0; ma < 2; ma++)
                #pragma unroll
                for (int na = 0; na < 4; na++)
                    mma_tf32(acc[ma][na], afr[ma], bfr[na]);
        }
    };

    // ---- prologue ----
    int4 A0, A1;
    cp_h(0);
    ld_adj(0, A0);
    ld_adj(1, A1);
    CP_WAIT0();
    __syncthreads();
    store_p(0, A0);
    ld_adj(2, A0);
    __syncthreads();

    // ---- main loop (x2 unroll for adj register ping-pong) ----
    for (int jt = 0; jt < 64; jt += 2) {
        {
            if (jt < 63) cp_h(jt + 1);
            do_mma(jt);
            if (jt < 63) store_p(jt + 1, A1);
            if (jt + 3 < 64) ld_adj(jt + 3, A1);
            if (jt < 63) CP_WAIT0();
            __syncthreads();
        }
        {
            int jo = jt + 1;
            if (jo < 63) cp_h(jo + 1);
            do_mma(jo);
            if (jo < 63) store_p(jo + 1, A0);
            if (jo + 3 < 64) ld_adj(jo + 3, A0);
            if (jo < 63) CP_WAIT0();
            __syncthreads();
        }
    }

    smf[AT_DSUM + jq * 128 + irow] = dloc;
    __syncthreads();

    #pragma unroll
    for (int ma = 0; ma < 2; ma++) {
        int ra = wiq * 32 + ma * 16 + g;
        int rb = ra + 8;
        float da = 0.f, db = 0.f;
        #pragma unroll
        for (int s = 0; s < 8; s++) {
            da += smf[AT_DSUM + s * 128 + ra];
            db += smf[AT_DSUM + s * 128 + rb];
        }
        float inva = (da > 0.f) ? 1.f / da : 0.f;
        float invb = (db > 0.f) ? 1.f / db : 0.f;
        float* outa = out + ((size_t)b * NN + i0 + ra) * FOUT;
        float* outb = out + ((size_t)b * NN + i0 + rb) * FOUT;
        #pragma unroll
        for (int na = 0; na < 4; na++) {
            int col = wo * 32 + na * 8 + tig * 2;
            float v0 = acc[ma][na][0] * inva;
            float v1 = acc[ma][na][1] * inva;
            float v2 = acc[ma][na][2] * invb;
            float v3 = acc[ma][na][3] * invb;
            v0 = v0 > 0.f ? v0 : expm1f(v0);
            v1 = v1 > 0.f ? v1 : expm1f(v1);
            v2 = v2 > 0.f ? v2 : expm1f(v2);
            v3 = v3 > 0.f ? v3 : expm1f(v3);
            *(float2*)(outa + col) = make_float2(v0, v1);
            *(float2*)(outb + col) = make_float2(v2, v3);
        }
    }
}

// ---------------------------------------------------------------------------
extern "C" void kernel_launch(void* const* d_in, const int* in_sizes, int n_in,
                              void* d_out, int out_size)
{
    const float* x   = (const float*)d_in[0];
    const int*   adj = (const int*)d_in[1];
    const float* W   = (const float*)d_in[2];
    const float* a   = (const float*)d_in[3];
    float*       out = (float*)d_out;

    cudaFuncSetAttribute(gemm_h_kernel, cudaFuncAttributeMaxDynamicSharedMemorySize, GH_SMEM);
    cudaFuncSetAttribute(attn_kernel,   cudaFuncAttributeMaxDynamicSharedMemorySize, ATTN_SMEM);

    gemm_h_kernel<<<128, 512, GH_SMEM>>>(x, W, a);
    attn_kernel<<<128, 1024, ATTN_SMEM>>>(adj, out);
}